// round 5
// baseline (speedup 1.0000x reference)
#include <cuda_runtime.h>
#include <math.h>
#include <stdint.h>

#define BB 64
#define SS 1024
#define EE 1024
#define DD 512

// ---------------- device scratch ----------------
__device__ float g_hp[BB * DD];            // h_proj + bias  [B, D]
__device__ float g_WeT[DD * EE];           // W_e^T, pre-rounded to tf32 [D(n), E2(k)]
__device__ float g_pscore[2 * BB * SS];    // per-n-tile score partials
__device__ float g_ctx_part[8 * BB * EE];  // context partials

// ---------------- helpers ----------------
__device__ __forceinline__ uint32_t smem_u32(const void* p) {
    uint32_t a;
    asm("{ .reg .u64 t; cvta.to.shared.u64 t, %1; cvt.u32.u64 %0, t; }" : "=r"(a) : "l"(p));
    return a;
}
#define CP_ASYNC16(dst, src) \
    asm volatile("cp.async.cg.shared.global [%0], [%1], 16;" :: "r"(dst), "l"(src) : "memory")
#define CP_COMMIT() asm volatile("cp.async.commit_group;" ::: "memory")
#define CP_WAIT2()  asm volatile("cp.async.wait_group 2;" ::: "memory")
#define CP_WAIT0()  asm volatile("cp.async.wait_group 0;" ::: "memory")

__device__ __forceinline__ uint32_t f2tf32(float x) {
    uint32_t u;
    asm("cvt.rna.tf32.f32 %0, %1;" : "=r"(u) : "f"(x));
    return u;
}

__device__ __forceinline__ void mma_tf32(float c[4], uint32_t a0, uint32_t a1,
                                         uint32_t a2, uint32_t a3, uint32_t b0,
                                         uint32_t b1) {
    asm volatile(
        "mma.sync.aligned.m16n8k8.row.col.f32.tf32.tf32.f32 "
        "{%0,%1,%2,%3}, {%4,%5,%6,%7}, {%8,%9}, {%0,%1,%2,%3};"
        : "+f"(c[0]), "+f"(c[1]), "+f"(c[2]), "+f"(c[3])
        : "r"(a0), "r"(a1), "r"(a2), "r"(a3), "r"(b0), "r"(b1));
}

// ---------------- tiling ----------------
#define BM 128
#define BN 256
#define BK 32
#define NCHUNK (EE / BK)        // 32
#define NSTAGE 3
#define ROWSTRIDE 48            // floats; 192B ≡ 64 mod 128 -> conflict-free LDS.128
#define A_SZB (BM * ROWSTRIDE * 4)   // 24576
#define B_SZB (BN * ROWSTRIDE * 4)   // 49152
#define STAGE_B (A_SZB + B_SZB)      // 73728
#define OFF_SHP (NSTAGE * STAGE_B)            // 221184: hp tile (256 floats)
#define OFF_SV  (OFF_SHP + BN * 4)            // v tile (256 floats)
#define OFF_RED 0                              // red[128][17] aliases stage 0 (dead)
#define SMEM_SIZE (OFF_SV + BN * 4)           // 223232 B

// ---------------------------------------------------------------------------
// transpose W_e [E2, D] -> g_WeT [D, E2], pre-rounded to tf32 (rna)
// ---------------------------------------------------------------------------
__global__ void transpose_we(const float* __restrict__ attn_W) {
    __shared__ float t[32][33];
    int k0 = blockIdx.x * 32, d0 = blockIdx.y * 32;
    for (int i = threadIdx.y; i < 32; i += 8)
        t[i][threadIdx.x] = attn_W[(size_t)(DD + k0 + i) * DD + d0 + threadIdx.x];
    __syncthreads();
    for (int i = threadIdx.y; i < 32; i += 8)
        g_WeT[(size_t)(d0 + i) * EE + k0 + threadIdx.x] =
            __uint_as_float(f2tf32(t[threadIdx.x][i]));
}

// ---------------------------------------------------------------------------
// hp[b,d] = attn_b[d] + hidden[b,:] @ attn_W[:D, d]   (exact fp32)
// ---------------------------------------------------------------------------
__global__ void hproj_kernel(const float* __restrict__ hidden,
                             const float* __restrict__ attn_W,
                             const float* __restrict__ attn_b) {
    __shared__ float hrow[DD];
    int b = blockIdx.y;
    int d = blockIdx.x * 128 + threadIdx.x;
    for (int i = threadIdx.x; i < DD; i += 128) hrow[i] = hidden[b * DD + i];
    __syncthreads();
    float acc = attn_b[d];
#pragma unroll 8
    for (int k = 0; k < DD; k++) acc += hrow[k] * attn_W[k * DD + d];
    g_hp[b * DD + d] = acc;
}

// ---------------------------------------------------------------------------
// scores: tf32 mma.sync GEMM (128x256 tile, K=1024), 3-stage cp.async,
// float4 (LDS.128) fragment loads via legal k-slot permutation:
// per 16-k block, lane (tig) covers physical k = 4*tig..4*tig+3;
// mma_x uses elems(0,1), mma_y elems(2,3) — A and B consistent.
// grid (2 n-tiles, 512 row-tiles), 256 threads (8 warps, each 64x64).
// ---------------------------------------------------------------------------
__global__ void __launch_bounds__(256, 1)
scores_mma_kernel(const float* __restrict__ enc, const float* __restrict__ vW) {
    extern __shared__ char smem[];
    uint32_t sb = smem_u32(smem);
    int tid = threadIdx.x;
    int wid = tid >> 5, lid = tid & 31;
    int gid = lid >> 2, tig = lid & 3;
    int wm = wid >> 2, wn = wid & 3;       // warp grid 2(m) x 4(n)
    int nt = blockIdx.x;                   // n tile (0..1)
    int r0 = blockIdx.y * BM;              // global row
    int b = r0 / SS;
    int n0 = nt * BN;

    float* shp = (float*)(smem + OFF_SHP);
    float* sv  = (float*)(smem + OFF_SV);
    for (int i = tid; i < BN; i += 256) {
        shp[i] = g_hp[b * DD + n0 + i];
        sv[i]  = vW[n0 + i];
    }

    const float* Abase = enc + (size_t)r0 * EE;
    const float* Bbase = g_WeT + (size_t)n0 * EE;

    auto load_chunk = [&](int c, int st) {
        uint32_t sA = sb + st * STAGE_B;
        uint32_t sB = sA + A_SZB;
#pragma unroll
        for (int i = 0; i < 4; i++) {                 // A: 1024 16B chunks
            int idx = tid + i * 256;
            int row = idx >> 3, ch = idx & 7;
            CP_ASYNC16(sA + row * (ROWSTRIDE * 4) + ch * 16,
                       Abase + (size_t)row * EE + c * BK + ch * 4);
        }
#pragma unroll
        for (int i = 0; i < 8; i++) {                 // B: 2048 16B chunks
            int idx = tid + i * 256;
            int row = idx >> 3, ch = idx & 7;
            CP_ASYNC16(sB + row * (ROWSTRIDE * 4) + ch * 16,
                       Bbase + (size_t)row * EE + c * BK + ch * 4);
        }
        CP_COMMIT();
    };

    float acc[4][8][4];
#pragma unroll
    for (int mf = 0; mf < 4; mf++)
#pragma unroll
        for (int nf = 0; nf < 8; nf++)
#pragma unroll
            for (int q = 0; q < 4; q++) acc[mf][nf][q] = 0.f;

    load_chunk(0, 0);
    load_chunk(1, 1);
    load_chunk(2, 2);

    int st = 0;
    for (int c = 0; c < NCHUNK; c++) {
        CP_WAIT2();
        __syncthreads();
        const float* fA = (const float*)(smem + st * STAGE_B);
        const float* fB = (const float*)(smem + st * STAGE_B + A_SZB);
#pragma unroll
        for (int k16 = 0; k16 < BK; k16 += 16) {
            // per-lane float4 covers physical k = k16 + 4*tig .. +3
            float4 alo[4], ahi[4], bv[8];
#pragma unroll
            for (int mf = 0; mf < 4; mf++) {
                int m0 = wm * 64 + mf * 16 + gid;
                alo[mf] = *(const float4*)&fA[m0 * ROWSTRIDE + k16 + 4 * tig];
                ahi[mf] = *(const float4*)&fA[(m0 + 8) * ROWSTRIDE + k16 + 4 * tig];
            }
#pragma unroll
            for (int nf = 0; nf < 8; nf++) {
                int nr = wn * 64 + nf * 8 + gid;
                bv[nf] = *(const float4*)&fB[nr * ROWSTRIDE + k16 + 4 * tig];
            }
            // mma_x: slot pair <- physical (4t, 4t+1)
#pragma unroll
            for (int mf = 0; mf < 4; mf++)
#pragma unroll
                for (int nf = 0; nf < 8; nf++)
                    mma_tf32(acc[mf][nf],
                             __float_as_uint(alo[mf].x), __float_as_uint(ahi[mf].x),
                             __float_as_uint(alo[mf].y), __float_as_uint(ahi[mf].y),
                             __float_as_uint(bv[nf].x), __float_as_uint(bv[nf].y));
            // mma_y: slot pair <- physical (4t+2, 4t+3)
#pragma unroll
            for (int mf = 0; mf < 4; mf++)
#pragma unroll
                for (int nf = 0; nf < 8; nf++)
                    mma_tf32(acc[mf][nf],
                             __float_as_uint(alo[mf].z), __float_as_uint(ahi[mf].z),
                             __float_as_uint(alo[mf].w), __float_as_uint(ahi[mf].w),
                             __float_as_uint(bv[nf].z), __float_as_uint(bv[nf].w));
        }
        __syncthreads();
        if (c + NSTAGE < NCHUNK) load_chunk(c + NSTAGE, st);
        st = (st == NSTAGE - 1) ? 0 : st + 1;
    }
    CP_WAIT0();
    __syncthreads();   // stages dead; red aliases stage 0

    // ---- epilogue: score partial = sum_n v[n] * tanh(acc + hp[n]) ----
    float* red = (float*)(smem + OFF_RED);  // [128][17]
#pragma unroll
    for (int mf = 0; mf < 4; mf++) {
#pragma unroll
        for (int half = 0; half < 2; half++) {
            int r = wm * 64 + mf * 16 + half * 8 + gid;
            float s = 0.f;
#pragma unroll
            for (int nf = 0; nf < 8; nf++) {
                int nl = wn * 64 + nf * 8 + tig * 2;
                float e0 = acc[mf][nf][half * 2 + 0] + shp[nl];
                float e1 = acc[mf][nf][half * 2 + 1] + shp[nl + 1];
                float t0, t1;
                asm("tanh.approx.f32 %0, %1;" : "=f"(t0) : "f"(e0));
                asm("tanh.approx.f32 %0, %1;" : "=f"(t1) : "f"(e1));
                s = fmaf(sv[nl], t0, s);
                s = fmaf(sv[nl + 1], t1, s);
            }
            red[r * 17 + wn * 4 + tig] = s;
        }
    }
    __syncthreads();
    if (tid < BM) {
        float s = 0.f;
#pragma unroll
        for (int t = 0; t < 16; t++) s += red[tid * 17 + t];
        g_pscore[nt * (BB * SS) + r0 + tid] = s;
    }
}

// ---------------------------------------------------------------------------
// softmax: combine 2 partials, mask, softmax over S. grid(64), 256 threads.
// ---------------------------------------------------------------------------
__global__ void softmax_kernel(const int* __restrict__ mask,
                               float* __restrict__ wout) {
    int b = blockIdx.x;
    __shared__ float sc[SS];
    __shared__ float redbuf[256];
    int tid = threadIdx.x;

    float lmax = -3.402823466e38f;
    for (int s = tid; s < SS; s += 256) {
        int idx = b * SS + s;
        float v = g_pscore[idx] + g_pscore[BB * SS + idx];
        if (mask[idx] == 0) v = -3.402823466e38f;
        sc[s] = v;
        lmax = fmaxf(lmax, v);
    }
    redbuf[tid] = lmax;
    __syncthreads();
    for (int o = 128; o > 0; o >>= 1) {
        if (tid < o) redbuf[tid] = fmaxf(redbuf[tid], redbuf[tid + o]);
        __syncthreads();
    }
    float m = redbuf[0];
    __syncthreads();

    float lsum = 0.f;
    for (int s = tid; s < SS; s += 256) {
        float e = expf(sc[s] - m);
        sc[s] = e;
        lsum += e;
    }
    redbuf[tid] = lsum;
    __syncthreads();
    for (int o = 128; o > 0; o >>= 1) {
        if (tid < o) redbuf[tid] += redbuf[tid + o];
        __syncthreads();
    }
    float inv = 1.f / redbuf[0];
    for (int s = tid; s < SS; s += 256) wout[b * SS + s] = sc[s] * inv;
}

// ---------------------------------------------------------------------------
// context partials: grid (2, 8, 64), 128 threads; float4 per thread.
// ---------------------------------------------------------------------------
__global__ void __launch_bounds__(128) context_part_kernel(
    const float* __restrict__ enc, const float* __restrict__ w) {
    __shared__ float ws[128];
    int bx = blockIdx.x, sy = blockIdx.y, b = blockIdx.z;
    int e0 = bx * 512 + threadIdx.x * 4;
    ws[threadIdx.x] = w[b * SS + sy * 128 + threadIdx.x];
    __syncthreads();
    const float* base = enc + ((size_t)b * SS + sy * 128) * EE + e0;
    float4 acc = make_float4(0.f, 0.f, 0.f, 0.f);
#pragma unroll 4
    for (int r = 0; r < 128; r++) {
        float4 v = *(const float4*)(base + (size_t)r * EE);
        float c = ws[r];
        acc.x = fmaf(c, v.x, acc.x);
        acc.y = fmaf(c, v.y, acc.y);
        acc.z = fmaf(c, v.z, acc.z);
        acc.w = fmaf(c, v.w, acc.w);
    }
    *(float4*)&g_ctx_part[((size_t)sy * BB + b) * EE + e0] = acc;
}

__global__ void context_reduce_kernel(float* __restrict__ ctx) {
    int b = blockIdx.y;
    int e = blockIdx.x * 256 + threadIdx.x;
    float s = 0.f;
#pragma unroll
    for (int sy = 0; sy < 8; sy++) s += g_ctx_part[((size_t)sy * BB + b) * EE + e];
    ctx[b * EE + e] = s;
}

// ---------------------------------------------------------------------------
extern "C" void kernel_launch(void* const* d_in, const int* in_sizes, int n_in,
                              void* d_out, int out_size) {
    const float* hidden = (const float*)d_in[0];   // [B, D]
    const float* enc    = (const float*)d_in[1];   // [B, S, E2]
    const int*   mask   = (const int*)d_in[2];     // [B, S]
    const float* attn_W = (const float*)d_in[3];   // [E2+D, D]
    const float* attn_b = (const float*)d_in[4];   // [D]
    const float* v_W    = (const float*)d_in[5];   // [D]

    float* out = (float*)d_out;
    float* ctx = out;            // context [B, E2]
    float* wts = out + BB * EE;  // attn_weights [B, S]

    cudaFuncSetAttribute(scores_mma_kernel,
                         cudaFuncAttributeMaxDynamicSharedMemorySize, SMEM_SIZE);

    transpose_we<<<dim3(EE / 32, DD / 32), dim3(32, 8)>>>(attn_W);
    hproj_kernel<<<dim3(DD / 128, BB), 128>>>(hidden, attn_W, attn_b);
    scores_mma_kernel<<<dim3(2, (BB * SS) / BM), 256, SMEM_SIZE>>>(enc, v_W);
    softmax_kernel<<<BB, 256>>>(mask, wts);
    context_part_kernel<<<dim3(2, 8, BB), 128>>>(enc, wts);
    context_reduce_kernel<<<dim3(4, BB), 256>>>(ctx);
}

// round 7
// speedup vs baseline: 1.1218x; 1.1218x over previous
#include <cuda_runtime.h>
#include <cuda_fp16.h>
#include <math.h>
#include <stdint.h>
#include <string.h>

#define BB 64
#define SS 1024
#define EE 1024
#define DD 512

// ---------------- device scratch ----------------
__device__ float  g_hp[BB * DD];            // h_proj + bias  [B, D]
__device__ __half g_ench[(size_t)BB * SS * EE];  // enc in fp16 (134 MB)
__device__ __half g_WeTh[DD * EE];          // W_e^T in fp16 [D(n), E2(k)]
__device__ float  g_pscore[2 * BB * SS];    // per-n-tile score partials
__device__ float  g_ctx_part[8 * BB * EE];  // context partials

// ---------------- helpers ----------------
__device__ __forceinline__ uint32_t smem_u32(const void* p) {
    uint32_t a;
    asm("{ .reg .u64 t; cvta.to.shared.u64 t, %1; cvt.u32.u64 %0, t; }" : "=r"(a) : "l"(p));
    return a;
}
#define CP_ASYNC16(dst, src) \
    asm volatile("cp.async.cg.shared.global [%0], [%1], 16;" :: "r"(dst), "l"(src) : "memory")
#define CP_COMMIT() asm volatile("cp.async.commit_group;" ::: "memory")
#define CP_WAIT3()  asm volatile("cp.async.wait_group 3;" ::: "memory")
#define CP_WAIT0()  asm volatile("cp.async.wait_group 0;" ::: "memory")

__device__ __forceinline__ uint32_t pack_half2(float lo, float hi) {
    uint32_t r;
    asm("cvt.rn.f16x2.f32 %0, %1, %2;" : "=r"(r) : "f"(hi), "f"(lo));
    return r;
}

__device__ __forceinline__ void mma_f16(float c[4], uint32_t a0, uint32_t a1,
                                        uint32_t a2, uint32_t a3, uint32_t b0,
                                        uint32_t b1) {
    asm volatile(
        "mma.sync.aligned.m16n8k16.row.col.f32.f16.f16.f32 "
        "{%0,%1,%2,%3}, {%4,%5,%6,%7}, {%8,%9}, {%0,%1,%2,%3};"
        : "+f"(c[0]), "+f"(c[1]), "+f"(c[2]), "+f"(c[3])
        : "r"(a0), "r"(a1), "r"(a2), "r"(a3), "r"(b0), "r"(b1));
}

// ---------------- tiling ----------------
#define BM 128
#define BN 256
#define BK 32
#define NCHUNK (EE / BK)        // 32
#define NSTAGE 4
#define RSB 80                  // row stride BYTES (64 data + 16 pad)
#define A_SZB (BM * RSB)        // 10240
#define B_SZB (BN * RSB)        // 20480
#define STAGE_B (A_SZB + B_SZB) // 30720
#define OFF_SHP (NSTAGE * STAGE_B)            // 122880: hp tile (256 floats)
#define OFF_SV  (OFF_SHP + BN * 4)            // v tile (256 floats)
#define OFF_RED 0                             // red[128][17] aliases stage 0 (dead)
#define SMEM_SIZE (OFF_SV + BN * 4)           // 124928 B

// ---------------------------------------------------------------------------
// convert enc f32 -> fp16. grid 32768 x 256 thr, 8 elems/thread.
// ---------------------------------------------------------------------------
__global__ void __launch_bounds__(256) convert_enc(const float* __restrict__ enc) {
    size_t base = ((size_t)blockIdx.x * 256 + threadIdx.x) * 8;
    float4 v0 = *(const float4*)(enc + base);
    float4 v1 = *(const float4*)(enc + base + 4);
    uint4 o;
    o.x = pack_half2(v0.x, v0.y);
    o.y = pack_half2(v0.z, v0.w);
    o.z = pack_half2(v1.x, v1.y);
    o.w = pack_half2(v1.z, v1.w);
    *(uint4*)(&g_ench[base]) = o;
}

// ---------------------------------------------------------------------------
// transpose W_e [E2, D] -> g_WeTh [D, E2] fp16 (rn)
// ---------------------------------------------------------------------------
__global__ void transpose_we(const float* __restrict__ attn_W) {
    __shared__ float t[32][33];
    int k0 = blockIdx.x * 32, d0 = blockIdx.y * 32;
    for (int i = threadIdx.y; i < 32; i += 8)
        t[i][threadIdx.x] = attn_W[(size_t)(DD + k0 + i) * DD + d0 + threadIdx.x];
    __syncthreads();
    for (int i = threadIdx.y; i < 32; i += 8)
        g_WeTh[(size_t)(d0 + i) * EE + k0 + threadIdx.x] = __float2half_rn(t[threadIdx.x][i]);
}

// ---------------------------------------------------------------------------
// hp[b,d] = attn_b[d] + hidden[b,:] @ attn_W[:D, d]   (exact fp32)
// ---------------------------------------------------------------------------
__global__ void hproj_kernel(const float* __restrict__ hidden,
                             const float* __restrict__ attn_W,
                             const float* __restrict__ attn_b) {
    __shared__ float hrow[DD];
    int b = blockIdx.y;
    int d = blockIdx.x * 128 + threadIdx.x;
    for (int i = threadIdx.x; i < DD; i += 128) hrow[i] = hidden[b * DD + i];
    __syncthreads();
    float acc = attn_b[d];
#pragma unroll 8
    for (int k = 0; k < DD; k++) acc += hrow[k] * attn_W[k * DD + d];
    g_hp[b * DD + d] = acc;
}

// ---------------------------------------------------------------------------
// scores: fp16 m16n8k16 GEMM (128x256 tile, K=1024), 4-stage cp.async.
// k-slot permutation: within each 32-k chunk, lane tig owns physical
// k = [8*tig, 8*tig+8): one LDS.128 per fragment row. instr j (of 2 per
// chunk) takes half-pairs (2j, 2j+1) of that 8-half vector; A and B use the
// identical assignment, so the contraction is exact. C layout unchanged.
// grid (2 n-tiles, 512 row-tiles), 256 threads (8 warps, each 64x64).
// ---------------------------------------------------------------------------
__global__ void __launch_bounds__(256, 1)
scores_mma_kernel(const float* __restrict__ vW) {
    extern __shared__ char smem[];
    uint32_t sb = smem_u32(smem);
    int tid = threadIdx.x;
    int wid = tid >> 5, lid = tid & 31;
    int gid = lid >> 2, tig = lid & 3;
    int wm = wid >> 2, wn = wid & 3;       // warp grid 2(m) x 4(n)
    int nt = blockIdx.x;                   // n tile (0..1)
    int r0 = blockIdx.y * BM;              // global row
    int b = r0 / SS;
    int n0 = nt * BN;

    float* shp = (float*)(smem + OFF_SHP);
    float* sv  = (float*)(smem + OFF_SV);
    for (int i = tid; i < BN; i += 256) {
        shp[i] = g_hp[b * DD + n0 + i];
        sv[i]  = vW[n0 + i];
    }

    const __half* Abase = g_ench + (size_t)r0 * EE;
    const __half* Bbase = g_WeTh + (size_t)n0 * EE;

    auto load_chunk = [&](int c, int st) {
        uint32_t sA = sb + st * STAGE_B;
        uint32_t sB = sA + A_SZB;
#pragma unroll
        for (int i = 0; i < 2; i++) {                 // A: 512 16B chunks
            int idx = tid + i * 256;
            int row = idx >> 2, ch = idx & 3;
            CP_ASYNC16(sA + row * RSB + ch * 16,
                       Abase + (size_t)row * EE + c * BK + ch * 8);
        }
#pragma unroll
        for (int i = 0; i < 4; i++) {                 // B: 1024 16B chunks
            int idx = tid + i * 256;
            int row = idx >> 2, ch = idx & 3;
            CP_ASYNC16(sB + row * RSB + ch * 16,
                       Bbase + (size_t)row * EE + c * BK + ch * 8);
        }
        CP_COMMIT();
    };

    float acc[4][8][4];
#pragma unroll
    for (int mf = 0; mf < 4; mf++)
#pragma unroll
        for (int nf = 0; nf < 8; nf++)
#pragma unroll
            for (int q = 0; q < 4; q++) acc[mf][nf][q] = 0.f;

    load_chunk(0, 0);
    load_chunk(1, 1);
    load_chunk(2, 2);
    load_chunk(3, 3);

    int st = 0;
    for (int c = 0; c < NCHUNK; c++) {
        CP_WAIT3();
        __syncthreads();
        const char* fA = smem + st * STAGE_B;
        const char* fB = smem + st * STAGE_B + A_SZB;

        uint4 alo[4], ahi[4], bv[8];   // 8 halves each: phys k = 8*tig..+7
#pragma unroll
        for (int mf = 0; mf < 4; mf++) {
            int m0 = wm * 64 + mf * 16 + gid;
            alo[mf] = *(const uint4*)(fA + m0 * RSB + tig * 16);
            ahi[mf] = *(const uint4*)(fA + (m0 + 8) * RSB + tig * 16);
        }
#pragma unroll
        for (int nf = 0; nf < 8; nf++) {
            int nr = wn * 64 + nf * 8 + gid;
            bv[nf] = *(const uint4*)(fB + nr * RSB + tig * 16);
        }
        // instr 0: half-pairs 0,1 (phys k 8t..8t+3)
#pragma unroll
        for (int mf = 0; mf < 4; mf++)
#pragma unroll
            for (int nf = 0; nf < 8; nf++)
                mma_f16(acc[mf][nf], alo[mf].x, ahi[mf].x, alo[mf].y, ahi[mf].y,
                        bv[nf].x, bv[nf].y);
        // instr 1: half-pairs 2,3 (phys k 8t+4..8t+7)
#pragma unroll
        for (int mf = 0; mf < 4; mf++)
#pragma unroll
            for (int nf = 0; nf < 8; nf++)
                mma_f16(acc[mf][nf], alo[mf].z, ahi[mf].z, alo[mf].w, ahi[mf].w,
                        bv[nf].z, bv[nf].w);

        __syncthreads();
        if (c + NSTAGE < NCHUNK) load_chunk(c + NSTAGE, st);
        st = (st == NSTAGE - 1) ? 0 : st + 1;
    }
    CP_WAIT0();
    __syncthreads();   // stages dead; red aliases stage 0

    // ---- epilogue: score partial = sum_n v[n] * tanh(acc + hp[n]) ----
    float* red = (float*)(smem + OFF_RED);  // [128][17]
#pragma unroll
    for (int mf = 0; mf < 4; mf++) {
#pragma unroll
        for (int half = 0; half < 2; half++) {
            int r = wm * 64 + mf * 16 + half * 8 + gid;
            float s = 0.f;
#pragma unroll
            for (int nf = 0; nf < 8; nf++) {
                int nl = wn * 64 + nf * 8 + tig * 2;
                float e0 = acc[mf][nf][half * 2 + 0] + shp[nl];
                float e1 = acc[mf][nf][half * 2 + 1] + shp[nl + 1];
                float t0, t1;
                asm("tanh.approx.f32 %0, %1;" : "=f"(t0) : "f"(e0));
                asm("tanh.approx.f32 %0, %1;" : "=f"(t1) : "f"(e1));
                s = fmaf(sv[nl], t0, s);
                s = fmaf(sv[nl + 1], t1, s);
            }
            red[r * 17 + wn * 4 + tig] = s;
        }
    }
    __syncthreads();
    if (tid < BM) {
        float s = 0.f;
#pragma unroll
        for (int t = 0; t < 16; t++) s += red[tid * 17 + t];
        g_pscore[nt * (BB * SS) + r0 + tid] = s;
    }
}

// ---------------------------------------------------------------------------
// softmax: combine 2 partials, mask, softmax over S. grid(64), 256 threads.
// ---------------------------------------------------------------------------
__global__ void softmax_kernel(const int* __restrict__ mask,
                               float* __restrict__ wout) {
    int b = blockIdx.x;
    __shared__ float sc[SS];
    __shared__ float redbuf[256];
    int tid = threadIdx.x;

    float lmax = -3.402823466e38f;
    for (int s = tid; s < SS; s += 256) {
        int idx = b * SS + s;
        float v = g_pscore[idx] + g_pscore[BB * SS + idx];
        if (mask[idx] == 0) v = -3.402823466e38f;
        sc[s] = v;
        lmax = fmaxf(lmax, v);
    }
    redbuf[tid] = lmax;
    __syncthreads();
    for (int o = 128; o > 0; o >>= 1) {
        if (tid < o) redbuf[tid] = fmaxf(redbuf[tid], redbuf[tid + o]);
        __syncthreads();
    }
    float m = redbuf[0];
    __syncthreads();

    float lsum = 0.f;
    for (int s = tid; s < SS; s += 256) {
        float e = expf(sc[s] - m);
        sc[s] = e;
        lsum += e;
    }
    redbuf[tid] = lsum;
    __syncthreads();
    for (int o = 128; o > 0; o >>= 1) {
        if (tid < o) redbuf[tid] += redbuf[tid + o];
        __syncthreads();
    }
    float inv = 1.f / redbuf[0];
    for (int s = tid; s < SS; s += 256) wout[b * SS + s] = sc[s] * inv;
}

// ---------------------------------------------------------------------------
// context partials: grid (2, 8, 64), 128 threads; float4 per thread.
// ---------------------------------------------------------------------------
__global__ void __launch_bounds__(128) context_part_kernel(
    const float* __restrict__ enc, const float* __restrict__ w) {
    __shared__ float ws[128];
    int bx = blockIdx.x, sy = blockIdx.y, b = blockIdx.z;
    int e0 = bx * 512 + threadIdx.x * 4;
    ws[threadIdx.x] = w[b * SS + sy * 128 + threadIdx.x];
    __syncthreads();
    const float* base = enc + ((size_t)b * SS + sy * 128) * EE + e0;
    float4 acc = make_float4(0.f, 0.f, 0.f, 0.f);
#pragma unroll 8
    for (int r = 0; r < 128; r++) {
        float4 v = *(const float4*)(base + (size_t)r * EE);
        float c = ws[r];
        acc.x = fmaf(c, v.x, acc.x);
        acc.y = fmaf(c, v.y, acc.y);
        acc.z = fmaf(c, v.z, acc.z);
        acc.w = fmaf(c, v.w, acc.w);
    }
    *(float4*)&g_ctx_part[((size_t)sy * BB + b) * EE + e0] = acc;
}

__global__ void context_reduce_kernel(float* __restrict__ ctx) {
    int b = blockIdx.y;
    int e = blockIdx.x * 256 + threadIdx.x;
    float s = 0.f;
#pragma unroll
    for (int sy = 0; sy < 8; sy++) s += g_ctx_part[((size_t)sy * BB + b) * EE + e];
    ctx[b * EE + e] = s;
}

// ---------------------------------------------------------------------------
extern "C" void kernel_launch(void* const* d_in, const int* in_sizes, int n_in,
                              void* d_out, int out_size) {
    const float* hidden = (const float*)d_in[0];   // [B, D]
    const float* enc    = (const float*)d_in[1];   // [B, S, E2]
    const int*   mask   = (const int*)d_in[2];     // [B, S]
    const float* attn_W = (const float*)d_in[3];   // [E2+D, D]
    const float* attn_b = (const float*)d_in[4];   // [D]
    const float* v_W    = (const float*)d_in[5];   // [D]

    float* out = (float*)d_out;
    float* ctx = out;            // context [B, E2]
    float* wts = out + BB * EE;  // attn_weights [B, S]

    cudaFuncSetAttribute(scores_mma_kernel,
                         cudaFuncAttributeMaxDynamicSharedMemorySize, SMEM_SIZE);

    convert_enc<<<(BB * SS * EE) / (256 * 8), 256>>>(enc);
    transpose_we<<<dim3(EE / 32, DD / 32), dim3(32, 8)>>>(attn_W);
    hproj_kernel<<<dim3(DD / 128, BB), 128>>>(hidden, attn_W, attn_b);
    scores_mma_kernel<<<dim3(2, (BB * SS) / BM), 256, SMEM_SIZE>>>(v_W);
    softmax_kernel<<<BB, 256>>>(mask, wts);
    context_part_kernel<<<dim3(2, 8, BB), 128>>>(enc, wts);
    context_reduce_kernel<<<dim3(4, BB), 256>>>(ctx);
}